// round 13
// baseline (speedup 1.0000x reference)
#include <cuda_runtime.h>
#include <cuda_fp16.h>
#include <cstdint>

#define NN 100000
#define NE 3200000
#define HD 128
#define HD2 256
#define NL 4
#define NG 512
#define CSRB 296
#define CSRT 512
#define CHUNK 338    // ceil(NN/296)
#define EMB_B 50000  // embed blocks (NN*HD/256)
#define PK_B 512     // pack blocks per weight tensor

// ---------------- PTX helpers (all plain-sm_103 legal) -------------------------
__device__ __forceinline__ uint32_t smem_u32(const void* p) {
    uint32_t a;
    asm("{ .reg .u64 t; cvta.to.shared.u64 t, %1; cvt.u32.u64 %0, t; }" : "=r"(a) : "l"(p));
    return a;
}
#define LDSM4(r, a) \
    asm volatile("ldmatrix.sync.aligned.m8n8.x4.shared.b16 {%0,%1,%2,%3}, [%4];" \
        : "=r"((r)[0]), "=r"((r)[1]), "=r"((r)[2]), "=r"((r)[3]) : "r"(a))
#define MMA16816H(d, a, b0, b1) \
    asm volatile("mma.sync.aligned.m16n8k16.row.col.f32.f16.f16.f32 " \
        "{%0,%1,%2,%3}, {%4,%5,%6,%7}, {%8,%9}, {%0,%1,%2,%3};" \
        : "+f"((d)[0]), "+f"((d)[1]), "+f"((d)[2]), "+f"((d)[3]) \
        : "r"((a)[0]), "r"((a)[1]), "r"((a)[2]), "r"((a)[3]), "r"(b0), "r"(b1))
#define CP_ASYNC16(s, g, sz) \
    asm volatile("cp.async.cg.shared.global [%0], [%1], 16, %2;" :: "r"(s), "l"(g), "r"(sz))
#define CP_COMMIT() asm volatile("cp.async.commit_group;")
#define CP_WAIT0()  asm volatile("cp.async.wait_group 0;")
#define CP_WAIT1()  asm volatile("cp.async.wait_group 1;")
#define BAR_SYNC(id) asm volatile("bar.sync %0, 128;" :: "r"(id) : "memory")

// ---------------- device scratch ----------------------------------------------
__device__ __align__(16) float   g_h[NN * HD];               // fp32 h (last layer, pool)
__device__ __align__(16) __half  g_h16[NN * HD];             // fp16 h (gather input)
__device__ __align__(16) __half  g_u16[(size_t)NN * HD2];    // fp16 u (GEMM2 A)
__device__ __align__(16) __half  g_B1h[NL * HD2 * HD];       // [l][n=256][k=128] fp16
__device__ __align__(16) __half  g_B2h[NL * HD * HD2];       // [l][n=128][k=256] fp16
__device__ int g_deg[NN], g_rowptr[NN + 1], g_cursor[NN], g_col[NE];
__device__ int g_part[CSRB], g_poff[CSRB];
__device__ volatile int g_bar;                               // reset by k_pool

// ---------------- grid-wide barrier (296 co-resident CTAs, 2/SM) ----------------
__device__ __forceinline__ void gridbar(int phase) {
    __syncthreads();
    if (threadIdx.x == 0) {
        __threadfence();
        atomicAdd((int*)&g_bar, 1);
        while (g_bar < CSRB * phase) { }
        __threadfence();
    }
    __syncthreads();
}

// ---------------- fused CSR build (one launch, 296x512) ------------------------
__global__ void __launch_bounds__(CSRT, 2) k_csr(const int* __restrict__ ei) {
    const int tid = threadIdx.x, bid = blockIdx.x;
    const int gstride = CSRB * CSRT;
    const int gtid = bid * CSRT + tid;
    __shared__ int s[CSRT];

    for (int i = gtid; i < NN; i += gstride) g_deg[i] = 0;
    gridbar(1);
    for (int e = gtid; e < NE; e += gstride) atomicAdd(&g_deg[ei[NE + e]], 1);
    gridbar(2);
    const int start = bid * CHUNK;
    const int end = (start + CHUNK < NN) ? start + CHUNK : NN;
    const int i0 = start + tid;
    int own = (i0 < end) ? g_deg[i0] : 0;
    s[tid] = own;
    __syncthreads();
    for (int off = 1; off < CSRT; off <<= 1) {
        int t = (tid >= off) ? s[tid - off] : 0;
        __syncthreads(); s[tid] += t; __syncthreads();
    }
    const int texcl = s[tid] - own;
    if (tid == CSRT - 1) g_part[bid] = s[tid];
    gridbar(3);
    if (bid == 0 && tid == 0) {
        int r = 0;
        for (int b = 0; b < CSRB; b++) { g_poff[b] = r; r += g_part[b]; }
    }
    gridbar(4);
    if (i0 < end) {
        int run = g_poff[bid] + texcl;
        g_rowptr[i0] = run;
        g_cursor[i0] = run;
    }
    if (gtid == 0) g_rowptr[NN] = NE;
    gridbar(5);
    for (int e = gtid; e < NE; e += gstride) {
        int p = atomicAdd(&g_cursor[ei[NE + e]], 1);
        g_col[p] = ei[e];
    }
}

// ---------------- embed + pack W1 ------------------------------------------------
__global__ void k_embed_pack(const float* __restrict__ x, const float* __restrict__ Wemb,
                             const float* __restrict__ bemb, const float* __restrict__ W1) {
    int bid = blockIdx.x;
    int tid = threadIdx.x;
    if (bid < EMB_B) {
        int idx = bid * 256 + tid;
        int n = idx >> 7, c = idx & 127;
        const float* xr = x + n * 9;
        float acc = bemb[c];
#pragma unroll
        for (int k = 0; k < 9; k++) acc = fmaf(xr[k], Wemb[k * HD + c], acc);
        g_h16[idx] = __float2half(acc);
    } else {
        int idx = (bid - EMB_B) * 256 + tid;        // NL*256*128
        int l = idx / (HD2 * HD), rem = idx % (HD2 * HD);
        int n = rem / HD, k = rem % HD;
        float w = W1[((size_t)l * HD + k) * HD2 + n];
        g_B1h[(size_t)l * HD2 * HD + (size_t)n * HD + k] = __float2half(w);
    }
}

// ---------------- pack W2 (separate launch: keeps fused kernel at launch #4) ----
__global__ void k_packW2(const float* __restrict__ W2) {
    int idx = blockIdx.x * blockDim.x + threadIdx.x;     // NL*128*256
    if (idx >= NL * HD * HD2) return;
    int l = idx / (HD * HD2), rem = idx % (HD * HD2);
    int n = rem / HD2, k = rem % HD2;
    float w = W2[((size_t)l * HD2 + k) * HD + n];
    g_B2h[(size_t)l * HD * HD2 + (size_t)n * HD2 + k] = __float2half(w);
}

// ---------------- FUSED agg + GEMM1 + BN + ReLU ---------------------------------
// u16 = relu(BN( ((1+eps)h + sum_nbr h) @ W1 ))  [gather fused into A staging]
// 148 CTAs x 256 threads. Two independent 4-warp groups (named barriers), each
// with its own 32-row tile stream: gather (mem) of one group overlaps MMA
// (tensor) of the other. B slice per warp hoisted to registers (128 regs).
#define F_PB 272                       // B row pitch bytes
#define F_PA 272                       // A row pitch bytes
#define F_A0 0                         // group A buffers: 2 x 32 x 272 = 17408
#define F_B  17408                     // B: 256 x 272 = 69632
#define F_SAC 87040                    // Ac: 1024
#define F_SCC 88064                    // Cc: 1024
#define F_SM_TOTAL 89088

__global__ void __launch_bounds__(256, 1)
k_agg_gemm1(int l, const float* __restrict__ eps,
            const float* __restrict__ bb, const float* __restrict__ gm,
            const float* __restrict__ bt, const float* __restrict__ mn,
            const float* __restrict__ vr) {
    extern __shared__ char smem[];
    const uint32_t sb = smem_u32(smem);
    const int tid = threadIdx.x, lane = tid & 31;
    const int group = tid >> 7;            // 0 or 1 (warps 0-3 / 4-7)
    const int wig = (tid >> 5) & 3;        // warp in group
    const int barid = group + 1;

    const __half* Bsrc = g_B1h + (size_t)l * HD2 * HD;

    // ---- stage B (all 256 threads) + BN constants ------------------------------
    for (int c = tid; c < HD2 * 16; c += 256) {         // 4096 uint4
        int n = c >> 4, q = c & 15;
        CP_ASYNC16(sb + F_B + n * F_PB + q * 16, Bsrc + (size_t)c * 8, 16);
    }
    for (int c = tid; c < HD2; c += 256) {
        float a = gm[c] * rsqrtf(vr[c] + 1e-5f);
        ((float*)(smem + F_SAC))[c] = a;
        ((float*)(smem + F_SCC))[c] = fmaf(a, bb[c] - mn[c], bt[c]);
    }
    CP_COMMIT();
    CP_WAIT0();
    __syncthreads();

    // ---- hoist this warp's B slice: cols wig*64..+63, full K=128 ----------------
    const uint32_t lrow = (lane & 15), lcol = (lane >> 4) * 16;
    uint32_t bfr[8][4][4];
#pragma unroll
    for (int ks = 0; ks < 8; ks++)
#pragma unroll
        for (int np = 0; np < 4; np++) {
            uint32_t bAddr = sb + F_B + (wig * 64 + np * 16 + lrow) * F_PB + ks * 32 + lcol;
            LDSM4(bfr[ks][np], bAddr);
        }

    const float* Ac = (const float*)(smem + F_SAC);
    const float* Cc = (const float*)(smem + F_SCC);
    const uint32_t Ag = sb + F_A0 + group * 32 * F_PA;
    const float sc = 1.0f + eps[l];
    const uint2* h16 = (const uint2*)g_h16;

    // ---- per-group tile stream: 3125 tiles of exactly 32 rows ------------------
    for (int t = blockIdx.x * 2 + group; t < 3125; t += 296) {
        const int row0 = t * 32;

        // gather: warp wig handles rows row0+wig*8 .. +7; lane covers 8B of row
#pragma unroll 1
        for (int rr = 0; rr < 8; rr++) {
            const int node = row0 + wig * 8 + rr;
            uint2 sv = h16[(size_t)node * 32 + lane];
            float2 f0 = __half22float2(*(__half2*)&sv.x);
            float2 f1 = __half22float2(*(__half2*)&sv.y);
            float ax = f0.x * sc, ay = f0.y * sc, az = f1.x * sc, aw = f1.y * sc;
            int j = g_rowptr[node], e = g_rowptr[node + 1];
            for (; j + 3 < e; j += 4) {
                uint2 v0 = h16[(size_t)g_col[j]     * 32 + lane];
                uint2 v1 = h16[(size_t)g_col[j + 1] * 32 + lane];
                uint2 v2 = h16[(size_t)g_col[j + 2] * 32 + lane];
                uint2 v3 = h16[(size_t)g_col[j + 3] * 32 + lane];
                float2 f;
                f = __half22float2(*(__half2*)&v0.x); ax += f.x; ay += f.y;
                f = __half22float2(*(__half2*)&v0.y); az += f.x; aw += f.y;
                f = __half22float2(*(__half2*)&v1.x); ax += f.x; ay += f.y;
                f = __half22float2(*(__half2*)&v1.y); az += f.x; aw += f.y;
                f = __half22float2(*(__half2*)&v2.x); ax += f.x; ay += f.y;
                f = __half22float2(*(__half2*)&v2.y); az += f.x; aw += f.y;
                f = __half22float2(*(__half2*)&v3.x); ax += f.x; ay += f.y;
                f = __half22float2(*(__half2*)&v3.y); az += f.x; aw += f.y;
            }
            for (; j < e; j++) {
                uint2 v = h16[(size_t)g_col[j] * 32 + lane];
                float2 f;
                f = __half22float2(*(__half2*)&v.x); ax += f.x; ay += f.y;
                f = __half22float2(*(__half2*)&v.y); az += f.x; aw += f.y;
            }
            __half2 p0 = __floats2half2_rn(ax, ay);
            __half2 p1 = __floats2half2_rn(az, aw);
            *(uint2*)(smem + (Ag - sb) + (wig * 8 + rr) * F_PA + lane * 8) =
                make_uint2(*(uint32_t*)&p0, *(uint32_t*)&p1);
        }
        BAR_SYNC(barid);

        // MMA: warp covers 32 rows x 64 cols (cols wig*64..)
        float acc[2][8][4];
#pragma unroll
        for (int i = 0; i < 2; i++)
#pragma unroll
            for (int j = 0; j < 8; j++)
#pragma unroll
                for (int q = 0; q < 4; q++) acc[i][j][q] = 0.f;

#pragma unroll
        for (int ks = 0; ks < 8; ks++) {
            uint32_t ah[2][4];
#pragma unroll
            for (int i = 0; i < 2; i++)
                LDSM4(ah[i], Ag + (i * 16 + lrow) * F_PA + ks * 32 + lcol);
#pragma unroll
            for (int np = 0; np < 4; np++)
#pragma unroll
                for (int i = 0; i < 2; i++) {
                    MMA16816H(acc[i][2 * np],     ah[i], bfr[ks][np][0], bfr[ks][np][2]);
                    MMA16816H(acc[i][2 * np + 1], ah[i], bfr[ks][np][1], bfr[ks][np][3]);
                }
        }

        // epilogue: BN + ReLU -> u16
#pragma unroll
        for (int i = 0; i < 2; i++) {
#pragma unroll
            for (int j = 0; j < 8; j++) {
                int r0 = row0 + i * 16 + (lane >> 2);
                int r1 = r0 + 8;
                int c = wig * 64 + j * 8 + (lane & 3) * 2;
                float a0 = Ac[c], a1 = Ac[c + 1], c0 = Cc[c], c1 = Cc[c + 1];
                __half2 p0 = __floats2half2_rn(fmaxf(fmaf(acc[i][j][0], a0, c0), 0.f),
                                               fmaxf(fmaf(acc[i][j][1], a1, c1), 0.f));
                __half2 p1 = __floats2half2_rn(fmaxf(fmaf(acc[i][j][2], a0, c0), 0.f),
                                               fmaxf(fmaf(acc[i][j][3], a1, c1), 0.f));
                *(uint32_t*)(g_u16 + (size_t)r0 * HD2 + c) = *(uint32_t*)&p0;
                *(uint32_t*)(g_u16 + (size_t)r1 * HD2 + c) = *(uint32_t*)&p1;
            }
        }
        BAR_SYNC(barid);   // all group warps done with A before next gather
    }
}

// ---------------- GEMM2 + BN + ReLU (fp16, B in registers) ----------------------
// h16 (+h fp32 if last) = relu(BN(u @ W2)), KDIM=256, NOUT=128. (R12 kernel)
__global__ void __launch_bounds__(256, 1)
k_gemm2(int l, int last, const float* __restrict__ bb, const float* __restrict__ gm,
        const float* __restrict__ bt, const float* __restrict__ mn,
        const float* __restrict__ vr) {
    constexpr int KDIM = 256, NOUT = 128;
    constexpr int PC  = KDIM * 2 + 16;
    constexpr int PB  = KDIM * 2 + 16;
    constexpr int KS  = KDIM / 16;       // 16
    constexpr int NT  = NOUT / 32;       // 4
    constexpr int NW  = NOUT / 4;        // 32
    constexpr int RCA = KDIM / 8;        // 32
    constexpr int ACH = 64 * PC;
    constexpr int BHI = 2 * ACH;
    constexpr int SAC = BHI + NOUT * PB;
    constexpr int SCC = SAC + NOUT * 4;

    extern __shared__ char smem[];
    const uint32_t sb = smem_u32(smem);
    const int tid = threadIdx.x, wid = tid >> 5, lane = tid & 31;
    const int wm = wid & 1, wn = wid >> 1;

    const __half* in = g_u16;
    const __half* Bsrc = g_B2h + (size_t)l * HD * HD2;

    for (int c = tid; c < NOUT * RCA; c += 256) {
        int n = c / RCA, q = c % RCA;
        CP_ASYNC16(sb + BHI + n * PB + q * 16, Bsrc + (size_t)c * 8, 16);
    }
    for (int c = tid; c < NOUT; c += 256) {
        float a = gm[c] * rsqrtf(vr[c] + 1e-5f);
        ((float*)(smem + SAC))[c] = a;
        ((float*)(smem + SCC))[c] = fmaf(a, bb[c] - mn[c], bt[c]);
    }
    CP_COMMIT();
    CP_WAIT0();
    __syncthreads();

    const float* Ac = (const float*)(smem + SAC);
    const float* Cc = (const float*)(smem + SCC);
    const uint32_t lrow = (lane & 15), lcol = (lane >> 4) * 16;

    uint32_t bfr[KS][NT / 2][4];
#pragma unroll
    for (int ks = 0; ks < KS; ks++)
#pragma unroll
        for (int np = 0; np < NT / 2; np++) {
            uint32_t bAddr = sb + BHI + (wn * NW + np * 16 + lrow) * PB + ks * 32 + lcol;
            LDSM4(bfr[ks][np], bAddr);
        }

    const int tiles = (NN + 63) / 64;
    const int myTiles = (tiles > (int)blockIdx.x)
                        ? (tiles - blockIdx.x + gridDim.x - 1) / gridDim.x : 0;

    auto issueA = [&](int t, int buf) {
        int row0 = (blockIdx.x + t * gridDim.x) * 64;
        for (int c = tid; c < 64 * RCA; c += 256) {
            int r = c / RCA, q = c % RCA;
            int row = row0 + r;
            int ok = (row < NN);
            const void* g = in + (size_t)(ok ? row : 0) * KDIM + q * 8;
            CP_ASYNC16(sb + buf * ACH + r * PC + q * 16, g, ok ? 16 : 0);
        }
        CP_COMMIT();
    };

    if (myTiles > 0) issueA(0, 0);

    for (int t = 0; t < myTiles; t++) {
        const int buf = t & 1;
        const int row0 = (blockIdx.x + t * gridDim.x) * 64;
        __syncthreads();
        if (t + 1 < myTiles) { issueA(t + 1, (t + 1) & 1); CP_WAIT1(); }
        else                 { CP_WAIT0(); }
        __syncthreads();

        float acc[2][NT][4];
#pragma unroll
        for (int i = 0; i < 2; i++)
#pragma unroll
            for (int j = 0; j < NT; j++)
#pragma unroll
                for (int q = 0; q < 4; q++) acc[i][j][q] = 0.f;

#pragma unroll
        for (int ks = 0; ks < KS; ks++) {
            uint32_t ah[2][4];
#pragma unroll
            for (int i = 0; i < 2; i++)
                LDSM4(ah[i], sb + buf * ACH + (wm * 32 + i * 16 + lrow) * PC + ks * 32 + lcol);
#pragma unroll
            for (int np = 0; np < NT / 2; np++)
#pragma unroll
                for (int i = 0; i < 2; i++) {
                    MMA16816H(acc[i][2 * np],     ah[i], bfr[ks][np][0], bfr[ks][np][2]);
                    MMA16816H(acc[i][2 * np + 1], ah[i], bfr[ks][np][1], bfr[ks][np][3]);
                }
        }

#pragma unroll
        for (int i = 0; i < 2; i++) {
#pragma unroll
            for (int j = 0; j < NT; j++) {
                int r0 = row0 + wm * 32 + i * 16 + (lane >> 2);
                int r1 = r0 + 8;
                int c = wn * NW + j * 8 + (lane & 3) * 2;
                float a0 = Ac[c], a1 = Ac[c + 1], c0 = Cc[c], c1 = Cc[c + 1];
                float y00 = fmaxf(fmaf(acc[i][j][0], a0, c0), 0.f);
                float y01 = fmaxf(fmaf(acc[i][j][1], a1, c1), 0.f);
                float y10 = fmaxf(fmaf(acc[i][j][2], a0, c0), 0.f);
                float y11 = fmaxf(fmaf(acc[i][j][3], a1, c1), 0.f);
                if (r0 < NN) {
                    __half2 p = __floats2half2_rn(y00, y01);
                    *(uint32_t*)(g_h16 + (size_t)r0 * HD + c) = *(uint32_t*)&p;
                    if (last) *(float2*)(g_h + (size_t)r0 * HD + c) = make_float2(y00, y01);
                }
                if (r1 < NN) {
                    __half2 p = __floats2half2_rn(y10, y11);
                    *(uint32_t*)(g_h16 + (size_t)r1 * HD + c) = *(uint32_t*)&p;
                    if (last) *(float2*)(g_h + (size_t)r1 * HD + c) = make_float2(y10, y11);
                }
            }
        }
    }
}

// ---------------- global mean pool (+ barrier reset for next replay) ----------
__global__ void k_pool(const int* __restrict__ batch, float* __restrict__ out) {
    if (blockIdx.x == 0 && threadIdx.x == 0) g_bar = 0;
    int g = blockIdx.x, c = threadIdx.x;
    int lo = 0, hi = NN;
    while (lo < hi) { int mid = (lo + hi) >> 1; if (batch[mid] < g) lo = mid + 1; else hi = mid; }
    int start = lo;
    lo = start; hi = NN;
    while (lo < hi) { int mid = (lo + hi) >> 1; if (batch[mid] < g + 1) lo = mid + 1; else hi = mid; }
    int end = lo;
    float acc = 0.f;
    int n = start;
    for (; n + 3 < end; n += 4) {
        acc += g_h[(n + 0) * HD + c];
        acc += g_h[(n + 1) * HD + c];
        acc += g_h[(n + 2) * HD + c];
        acc += g_h[(n + 3) * HD + c];
    }
    for (; n < end; n++) acc += g_h[n * HD + c];
    float cnt = (float)(end - start);
    out[g * HD + c] = acc / fmaxf(cnt, 1.f);
}

// ---------------- launch --------------------------------------------------------
extern "C" void kernel_launch(void* const* d_in, const int* in_sizes, int n_in,
                              void* d_out, int out_size) {
    const float* x    = (const float*)d_in[0];
    const int*   ei   = (const int*)d_in[1];
    const int*   bat  = (const int*)d_in[2];
    const float* Wemb = (const float*)d_in[3];
    const float* bemb = (const float*)d_in[4];
    const float* eps  = (const float*)d_in[5];
    const float* W1   = (const float*)d_in[6];
    const float* b1   = (const float*)d_in[7];
    const float* g1   = (const float*)d_in[8];
    const float* be1  = (const float*)d_in[9];
    const float* m1   = (const float*)d_in[10];
    const float* v1   = (const float*)d_in[11];
    const float* W2   = (const float*)d_in[12];
    const float* b2   = (const float*)d_in[13];
    const float* g2   = (const float*)d_in[14];
    const float* be2  = (const float*)d_in[15];
    const float* m2   = (const float*)d_in[16];
    const float* v2   = (const float*)d_in[17];
    float* out = (float*)d_out;

    cudaFuncSetAttribute(k_agg_gemm1, cudaFuncAttributeMaxDynamicSharedMemorySize, F_SM_TOTAL);
    cudaFuncSetAttribute(k_gemm2, cudaFuncAttributeMaxDynamicSharedMemorySize, 136192);

    // order: embed+packW1(1), csr(2), packW2(3), fused(4) -> ncu profiles fused
    k_embed_pack<<<EMB_B + PK_B, 256>>>(x, Wemb, bemb, W1);          // 1
    k_csr<<<CSRB, CSRT>>>(ei);                                       // 2
    k_packW2<<<PK_B, 256>>>(W2);                                     // 3

    for (int l = 0; l < NL; l++) {
        k_agg_gemm1<<<148, 256, F_SM_TOTAL>>>(l, eps, b1 + l * HD2, g1 + l * HD2,
                                              be1 + l * HD2, m1 + l * HD2, v1 + l * HD2);
        k_gemm2<<<148, 256, 136192>>>(l, (l == NL - 1) ? 1 : 0,
                                      b2 + l * HD, g2 + l * HD,
                                      be2 + l * HD, m2 + l * HD, v2 + l * HD);
    }

    k_pool<<<NG, 128>>>(bat, out);
}

// round 14
// speedup vs baseline: 1.7345x; 1.7345x over previous
#include <cuda_runtime.h>
#include <cuda_fp16.h>
#include <cstdint>

#define NN 100000
#define NE 3200000
#define HD 128
#define HD2 256
#define NL 4
#define NG 512
#define CSRB 296
#define CSRT 512
#define CHUNK 338    // ceil(NN/296)
#define EMB_B 50000  // embed blocks (NN*HD/256)
#define PK_B 512     // pack blocks per weight tensor

// ---------------- PTX helpers (all plain-sm_103 legal) -------------------------
__device__ __forceinline__ uint32_t smem_u32(const void* p) {
    uint32_t a;
    asm("{ .reg .u64 t; cvta.to.shared.u64 t, %1; cvt.u32.u64 %0, t; }" : "=r"(a) : "l"(p));
    return a;
}
#define LDSM4(r, a) \
    asm volatile("ldmatrix.sync.aligned.m8n8.x4.shared.b16 {%0,%1,%2,%3}, [%4];" \
        : "=r"((r)[0]), "=r"((r)[1]), "=r"((r)[2]), "=r"((r)[3]) : "r"(a))
#define MMA16816H(d, a, b0, b1) \
    asm volatile("mma.sync.aligned.m16n8k16.row.col.f32.f16.f16.f32 " \
        "{%0,%1,%2,%3}, {%4,%5,%6,%7}, {%8,%9}, {%0,%1,%2,%3};" \
        : "+f"((d)[0]), "+f"((d)[1]), "+f"((d)[2]), "+f"((d)[3]) \
        : "r"((a)[0]), "r"((a)[1]), "r"((a)[2]), "r"((a)[3]), "r"(b0), "r"(b1))
#define CP_ASYNC16(s, g, sz) \
    asm volatile("cp.async.cg.shared.global [%0], [%1], 16, %2;" :: "r"(s), "l"(g), "r"(sz))
#define CP_COMMIT() asm volatile("cp.async.commit_group;")
#define CP_WAIT0()  asm volatile("cp.async.wait_group 0;")
#define CP_WAIT1()  asm volatile("cp.async.wait_group 1;")

// ---------------- device scratch ----------------------------------------------
__device__ __align__(16) float   g_h[NN * HD];               // fp32 h (last layer, pool)
__device__ __align__(16) __half  g_h16[NN * HD];             // fp16 h (gather input)
__device__ __align__(16) __half  g_z16[NN * HD];             // fp16 z (MLP A input)
__device__ __align__(16) __half  g_B1h[NL * HD2 * HD];       // [l][n=256][k=128] fp16
__device__ __align__(16) __half  g_B2h[NL * HD * HD2];       // [l][n=128][k=256] fp16
__device__ int g_deg[NN], g_rowptr[NN + 1], g_cursor[NN], g_col[NE];
__device__ int g_part[CSRB], g_poff[CSRB];
__device__ volatile int g_bar;                               // reset by k_pool

// ---------------- grid-wide barrier (296 co-resident CTAs, 2/SM) ----------------
__device__ __forceinline__ void gridbar(int phase) {
    __syncthreads();
    if (threadIdx.x == 0) {
        __threadfence();
        atomicAdd((int*)&g_bar, 1);
        while (g_bar < CSRB * phase) { }
        __threadfence();
    }
    __syncthreads();
}

// ---------------- fused CSR build (one launch, 296x512) ------------------------
__global__ void __launch_bounds__(CSRT, 2) k_csr(const int* __restrict__ ei) {
    const int tid = threadIdx.x, bid = blockIdx.x;
    const int gstride = CSRB * CSRT;
    const int gtid = bid * CSRT + tid;
    __shared__ int s[CSRT];

    for (int i = gtid; i < NN; i += gstride) g_deg[i] = 0;
    gridbar(1);
    for (int e = gtid; e < NE; e += gstride) atomicAdd(&g_deg[ei[NE + e]], 1);
    gridbar(2);
    const int start = bid * CHUNK;
    const int end = (start + CHUNK < NN) ? start + CHUNK : NN;
    const int i0 = start + tid;
    int own = (i0 < end) ? g_deg[i0] : 0;
    s[tid] = own;
    __syncthreads();
    for (int off = 1; off < CSRT; off <<= 1) {
        int t = (tid >= off) ? s[tid - off] : 0;
        __syncthreads(); s[tid] += t; __syncthreads();
    }
    const int texcl = s[tid] - own;
    if (tid == CSRT - 1) g_part[bid] = s[tid];
    gridbar(3);
    if (bid == 0 && tid == 0) {
        int r = 0;
        for (int b = 0; b < CSRB; b++) { g_poff[b] = r; r += g_part[b]; }
    }
    gridbar(4);
    if (i0 < end) {
        int run = g_poff[bid] + texcl;
        g_rowptr[i0] = run;
        g_cursor[i0] = run;
    }
    if (gtid == 0) g_rowptr[NN] = NE;
    gridbar(5);
    for (int e = gtid; e < NE; e += gstride) {
        int p = atomicAdd(&g_cursor[ei[NE + e]], 1);
        g_col[p] = ei[e];
    }
}

// ---------------- fused embed + pack W1 + pack W2 --------------------------------
__global__ void k_embed_pack(const float* __restrict__ x, const float* __restrict__ Wemb,
                             const float* __restrict__ bemb,
                             const float* __restrict__ W1, const float* __restrict__ W2) {
    int bid = blockIdx.x;
    int tid = threadIdx.x;
    if (bid < EMB_B) {
        int idx = bid * 256 + tid;
        int n = idx >> 7, c = idx & 127;
        const float* xr = x + n * 9;
        float acc = bemb[c];
#pragma unroll
        for (int k = 0; k < 9; k++) acc = fmaf(xr[k], Wemb[k * HD + c], acc);
        g_h16[idx] = __float2half(acc);
    } else if (bid < EMB_B + PK_B) {
        int idx = (bid - EMB_B) * 256 + tid;        // NL*256*128
        int l = idx / (HD2 * HD), rem = idx % (HD2 * HD);
        int n = rem / HD, k = rem % HD;
        float w = W1[((size_t)l * HD + k) * HD2 + n];
        g_B1h[(size_t)l * HD2 * HD + (size_t)n * HD + k] = __float2half(w);
    } else {
        int idx = (bid - EMB_B - PK_B) * 256 + tid; // NL*128*256
        int l = idx / (HD * HD2), rem = idx % (HD * HD2);
        int n = rem / HD2, k = rem % HD2;
        float w = W2[((size_t)l * HD2 + k) * HD + n];
        g_B2h[(size_t)l * HD * HD2 + (size_t)n * HD2 + k] = __float2half(w);
    }
}

// ---------------- GIN aggregation: fp16 gather, fp32 accumulate (R12 form) ------
__global__ void k_agg(const float* __restrict__ eps, int l) {
    int node = (blockIdx.x * blockDim.x + threadIdx.x) >> 5;
    if (node >= NN) return;
    int lane = threadIdx.x & 31;
    const uint2* h16 = (const uint2*)g_h16;
    float sc = 1.0f + eps[l];
    uint2 sv = h16[(size_t)node * 32 + lane];
    float2 f0 = __half22float2(*(__half2*)&sv.x);
    float2 f1 = __half22float2(*(__half2*)&sv.y);
    float ax = f0.x * sc, ay = f0.y * sc, az = f1.x * sc, aw = f1.y * sc;
    int j = g_rowptr[node], e = g_rowptr[node + 1];
    for (; j + 3 < e; j += 4) {
        uint2 v0 = h16[(size_t)g_col[j]     * 32 + lane];
        uint2 v1 = h16[(size_t)g_col[j + 1] * 32 + lane];
        uint2 v2 = h16[(size_t)g_col[j + 2] * 32 + lane];
        uint2 v3 = h16[(size_t)g_col[j + 3] * 32 + lane];
        float2 f;
        f = __half22float2(*(__half2*)&v0.x); ax += f.x; ay += f.y;
        f = __half22float2(*(__half2*)&v0.y); az += f.x; aw += f.y;
        f = __half22float2(*(__half2*)&v1.x); ax += f.x; ay += f.y;
        f = __half22float2(*(__half2*)&v1.y); az += f.x; aw += f.y;
        f = __half22float2(*(__half2*)&v2.x); ax += f.x; ay += f.y;
        f = __half22float2(*(__half2*)&v2.y); az += f.x; aw += f.y;
        f = __half22float2(*(__half2*)&v3.x); ax += f.x; ay += f.y;
        f = __half22float2(*(__half2*)&v3.y); az += f.x; aw += f.y;
    }
    for (; j < e; j++) {
        uint2 v = h16[(size_t)g_col[j] * 32 + lane];
        float2 f;
        f = __half22float2(*(__half2*)&v.x); ax += f.x; ay += f.y;
        f = __half22float2(*(__half2*)&v.y); az += f.x; aw += f.y;
    }
    __half2 p0 = __floats2half2_rn(ax, ay);
    __half2 p1 = __floats2half2_rn(az, aw);
    uint2 ov = make_uint2(*(uint32_t*)&p0, *(uint32_t*)&p1);
    __stcs((uint2*)(g_z16 + (size_t)node * HD) + lane, ov);
}

// ---------------- FUSED MLP: h = relu(BN2( relu(BN1(z@W1)) @ W2 )) ---------------
// 148 persistent CTAs x 256 threads, 64-row tiles. Phase 1 = R12 gemm1 (B1 in
// registers, acc 64), u tile kept in SMEM. Phase 2 = MMA vs B2 from smem.
// smem map (bytes):
//   [0, 34816)        A (z) double buffer: 2 x 64 x 272
//   [34816, 68608)    u tile: 64 x 528            (also B1 staging scratch)
//   [68608, 136192)   B2: 128 x 528
//   [136192..]        Ac1(1024) Cc1(1024) Ac2(512) Cc2(512)
#define M_PC   272
#define M_PU   528
#define M_ACH  17408      // 64*272
#define M_U    34816
#define M_B2   68608
#define M_AC1  136192
#define M_CC1  137216
#define M_AC2  138240
#define M_CC2  138752
#define M_TOTAL 139264

__global__ void __launch_bounds__(256, 1)
k_mlp(int l, int last,
      const float* __restrict__ b1, const float* __restrict__ g1,
      const float* __restrict__ be1, const float* __restrict__ m1,
      const float* __restrict__ v1,
      const float* __restrict__ b2, const float* __restrict__ g2,
      const float* __restrict__ be2, const float* __restrict__ m2,
      const float* __restrict__ v2) {
    extern __shared__ char smem[];
    const uint32_t sb = smem_u32(smem);
    const int tid = threadIdx.x, wid = tid >> 5, lane = tid & 31;
    const int wm = wid & 1, wn = wid >> 1;     // phase1: 32 rows x 64 cols; phase2: 32 rows x 32 cols
    const uint32_t lrow = (lane & 15), lcol = (lane >> 4) * 16;

    const __half* B1src = g_B1h + (size_t)l * HD2 * HD;
    const __half* B2src = g_B2h + (size_t)l * HD * HD2;

    // ---- stage B1 (scratch at M_U, pitch 272) + BN constants -------------------
    for (int c = tid; c < 4096; c += 256) {            // 256 rows x 16 uint4
        int n = c >> 4, q = c & 15;
        CP_ASYNC16(sb + M_U + n * M_PC + q * 16, B1src + (size_t)c * 8, 16);
    }
    for (int c = tid; c < HD2; c += 256) {
        float a = g1[c] * rsqrtf(v1[c] + 1e-5f);
        ((float*)(smem + M_AC1))[c] = a;
        ((float*)(smem + M_CC1))[c] = fmaf(a, b1[c] - m1[c], be1[c]);
    }
    for (int c = tid; c < HD; c += 256) {
        float a = g2[c] * rsqrtf(v2[c] + 1e-5f);
        ((float*)(smem + M_AC2))[c] = a;
        ((float*)(smem + M_CC2))[c] = fmaf(a, b2[c] - m2[c], be2[c]);
    }
    CP_COMMIT();
    CP_WAIT0();
    __syncthreads();

    // ---- hoist this warp's B1 slice (cols wn*64..+63, K=128) -> 128 regs -------
    uint32_t bfr[8][4][4];
#pragma unroll
    for (int ks = 0; ks < 8; ks++)
#pragma unroll
        for (int np = 0; np < 4; np++) {
            uint32_t bAddr = sb + M_U + (wn * 64 + np * 16 + lrow) * M_PC + ks * 32 + lcol;
            LDSM4(bfr[ks][np], bAddr);
        }
    __syncthreads();    // B1 scratch free before B2 staging overwrites overlap

    // ---- stage B2 (128 rows x 32 uint4, pitch 528) ------------------------------
    for (int c = tid; c < 4096; c += 256) {
        int n = c >> 5, q = c & 31;
        CP_ASYNC16(sb + M_B2 + n * M_PU + q * 16, B2src + (size_t)c * 8, 16);
    }
    CP_COMMIT();

    const float* Ac1 = (const float*)(smem + M_AC1);
    const float* Cc1 = (const float*)(smem + M_CC1);
    const float* Ac2 = (const float*)(smem + M_AC2);
    const float* Cc2 = (const float*)(smem + M_CC2);

    const int tiles = (NN + 63) / 64;
    const int myTiles = (tiles > (int)blockIdx.x)
                        ? (tiles - blockIdx.x + gridDim.x - 1) / gridDim.x : 0;

    auto issueA = [&](int t, int buf) {
        int row0 = (blockIdx.x + t * gridDim.x) * 64;
        for (int c = tid; c < 1024; c += 256) {        // 64 rows x 16 uint4
            int r = c >> 4, q = c & 15;
            int row = row0 + r;
            int ok = (row < NN);
            const void* g = g_z16 + (size_t)(ok ? row : 0) * HD + q * 8;
            CP_ASYNC16(sb + buf * M_ACH + r * M_PC + q * 16, g, ok ? 16 : 0);
        }
        CP_COMMIT();
    };

    if (myTiles > 0) issueA(0, 0);     // groups pending: B2, A0

    for (int t = 0; t < myTiles; t++) {
        const int buf = t & 1;
        const int row0 = (blockIdx.x + t * gridDim.x) * 64;
        __syncthreads();     // prev iter: all warps done with u tile + A[buf]
        if (t + 1 < myTiles) { issueA(t + 1, (t + 1) & 1); CP_WAIT1(); }
        else                 { CP_WAIT0(); }
        __syncthreads();     // A[buf] (and B2 on first iter) resident

        // ---- phase 1: acc1 = z @ W1 (B1 from registers) -------------------------
        float acc1[2][8][4];
#pragma unroll
        for (int i = 0; i < 2; i++)
#pragma unroll
            for (int j = 0; j < 8; j++)
#pragma unroll
                for (int q = 0; q < 4; q++) acc1[i][j][q] = 0.f;

#pragma unroll
        for (int ks = 0; ks < 8; ks++) {
            uint32_t ah[2][4];
#pragma unroll
            for (int i = 0; i < 2; i++)
                LDSM4(ah[i], sb + buf * M_ACH + (wm * 32 + i * 16 + lrow) * M_PC + ks * 32 + lcol);
#pragma unroll
            for (int np = 0; np < 4; np++)
#pragma unroll
                for (int i = 0; i < 2; i++) {
                    MMA16816H(acc1[i][2 * np],     ah[i], bfr[ks][np][0], bfr[ks][np][2]);
                    MMA16816H(acc1[i][2 * np + 1], ah[i], bfr[ks][np][1], bfr[ks][np][3]);
                }
        }

        // ---- epilogue 1: BN1 + ReLU -> u tile in smem ---------------------------
#pragma unroll
        for (int i = 0; i < 2; i++) {
#pragma unroll
            for (int j = 0; j < 8; j++) {
                int rl0 = wm * 32 + i * 16 + (lane >> 2);
                int rl1 = rl0 + 8;
                int c = wn * 64 + j * 8 + (lane & 3) * 2;
                float a0 = Ac1[c], a1 = Ac1[c + 1], c0 = Cc1[c], c1 = Cc1[c + 1];
                __half2 p0 = __floats2half2_rn(fmaxf(fmaf(acc1[i][j][0], a0, c0), 0.f),
                                               fmaxf(fmaf(acc1[i][j][1], a1, c1), 0.f));
                __half2 p1 = __floats2half2_rn(fmaxf(fmaf(acc1[i][j][2], a0, c0), 0.f),
                                               fmaxf(fmaf(acc1[i][j][3], a1, c1), 0.f));
                *(uint32_t*)(smem + M_U + rl0 * M_PU + c * 2) = *(uint32_t*)&p0;
                *(uint32_t*)(smem + M_U + rl1 * M_PU + c * 2) = *(uint32_t*)&p1;
            }
        }
        __syncthreads();     // u tile complete

        // ---- phase 2: acc2 = u @ W2 (u + B2 from smem) --------------------------
        float acc2[2][4][4];
#pragma unroll
        for (int i = 0; i < 2; i++)
#pragma unroll
            for (int j = 0; j < 4; j++)
#pragma unroll
                for (int q = 0; q < 4; q++) acc2[i][j][q] = 0.f;

#pragma unroll
        for (int ks = 0; ks < 16; ks++) {
            uint32_t ah[2][4];
#pragma unroll
            for (int i = 0; i < 2; i++)
                LDSM4(ah[i], sb + M_U + (wm * 32 + i * 16 + lrow) * M_PU + ks * 32 + lcol);
#pragma unroll
            for (int np = 0; np < 2; np++) {
                uint32_t bh[4];
                LDSM4(bh, sb + M_B2 + (wn * 32 + np * 16 + lrow) * M_PU + ks * 32 + lcol);
#pragma unroll
                for (int i = 0; i < 2; i++) {
                    MMA16816H(acc2[i][2 * np],     ah[i], bh[0], bh[2]);
                    MMA16816H(acc2[i][2 * np + 1], ah[i], bh[1], bh[3]);
                }
            }
        }

        // ---- epilogue 2: BN2 + ReLU -> h16 (+h fp32 if last) --------------------
#pragma unroll
        for (int i = 0; i < 2; i++) {
#pragma unroll
            for (int j = 0; j < 4; j++) {
                int r0 = row0 + wm * 32 + i * 16 + (lane >> 2);
                int r1 = r0 + 8;
                int c = wn * 32 + j * 8 + (lane & 3) * 2;
                float a0 = Ac2[c], a1 = Ac2[c + 1], c0 = Cc2[c], c1 = Cc2[c + 1];
                float y00 = fmaxf(fmaf(acc2[i][j][0], a0, c0), 0.f);
                float y01 = fmaxf(fmaf(acc2[i][j][1], a1, c1), 0.f);
                float y10 = fmaxf(fmaf(acc2[i][j][2], a0, c0), 0.f);
                float y11 = fmaxf(fmaf(acc2[i][j][3], a1, c1), 0.f);
                if (r0 < NN) {
                    __half2 p = __floats2half2_rn(y00, y01);
                    *(uint32_t*)(g_h16 + (size_t)r0 * HD + c) = *(uint32_t*)&p;
                    if (last) *(float2*)(g_h + (size_t)r0 * HD + c) = make_float2(y00, y01);
                }
                if (r1 < NN) {
                    __half2 p = __floats2half2_rn(y10, y11);
                    *(uint32_t*)(g_h16 + (size_t)r1 * HD + c) = *(uint32_t*)&p;
                    if (last) *(float2*)(g_h + (size_t)r1 * HD + c) = make_float2(y10, y11);
                }
            }
        }
    }
}

// ---------------- global mean pool (+ barrier reset for next replay) ----------
__global__ void k_pool(const int* __restrict__ batch, float* __restrict__ out) {
    if (blockIdx.x == 0 && threadIdx.x == 0) g_bar = 0;
    int g = blockIdx.x, c = threadIdx.x;
    int lo = 0, hi = NN;
    while (lo < hi) { int mid = (lo + hi) >> 1; if (batch[mid] < g) lo = mid + 1; else hi = mid; }
    int start = lo;
    lo = start; hi = NN;
    while (lo < hi) { int mid = (lo + hi) >> 1; if (batch[mid] < g + 1) lo = mid + 1; else hi = mid; }
    int end = lo;
    float acc = 0.f;
    int n = start;
    for (; n + 3 < end; n += 4) {
        acc += g_h[(n + 0) * HD + c];
        acc += g_h[(n + 1) * HD + c];
        acc += g_h[(n + 2) * HD + c];
        acc += g_h[(n + 3) * HD + c];
    }
    for (; n < end; n++) acc += g_h[n * HD + c];
    float cnt = (float)(end - start);
    out[g * HD + c] = acc / fmaxf(cnt, 1.f);
}

// ---------------- launch --------------------------------------------------------
extern "C" void kernel_launch(void* const* d_in, const int* in_sizes, int n_in,
                              void* d_out, int out_size) {
    const float* x    = (const float*)d_in[0];
    const int*   ei   = (const int*)d_in[1];
    const int*   bat  = (const int*)d_in[2];
    const float* Wemb = (const float*)d_in[3];
    const float* bemb = (const float*)d_in[4];
    const float* eps  = (const float*)d_in[5];
    const float* W1   = (const float*)d_in[6];
    const float* b1   = (const float*)d_in[7];
    const float* g1   = (const float*)d_in[8];
    const float* be1  = (const float*)d_in[9];
    const float* m1   = (const float*)d_in[10];
    const float* v1   = (const float*)d_in[11];
    const float* W2   = (const float*)d_in[12];
    const float* b2   = (const float*)d_in[13];
    const float* g2   = (const float*)d_in[14];
    const float* be2  = (const float*)d_in[15];
    const float* m2   = (const float*)d_in[16];
    const float* v2   = (const float*)d_in[17];
    float* out = (float*)d_out;

    cudaFuncSetAttribute(k_mlp, cudaFuncAttributeMaxDynamicSharedMemorySize, M_TOTAL);

    // order: embed+packs(1), csr(2), agg(3), mlp(4) -> ncu (launch #4) profiles mlp
    k_embed_pack<<<EMB_B + 2 * PK_B, 256>>>(x, Wemb, bemb, W1, W2);  // 1
    k_csr<<<CSRB, CSRT>>>(ei);                                       // 2

    for (int l = 0; l < NL; l++) {
        k_agg<<<(NN + 7) / 8, 256>>>(eps, l);                        // 3 (l=0)
        k_mlp<<<148, 256, M_TOTAL>>>(l, (l == NL - 1) ? 1 : 0,       // 4 (l=0)
                                     b1 + l * HD2, g1 + l * HD2, be1 + l * HD2,
                                     m1 + l * HD2, v1 + l * HD2,
                                     b2 + l * HD, g2 + l * HD, be2 + l * HD,
                                     m2 + l * HD, v2 + l * HD);
    }

    k_pool<<<NG, 128>>>(bat, out);
}

// round 15
// speedup vs baseline: 2.3616x; 1.3615x over previous
#include <cuda_runtime.h>
#include <cuda_fp16.h>
#include <cstdint>

#define NN 100000
#define NE 3200000
#define HD 128
#define HD2 256
#define NL 4
#define NG 512
#define CSRB 296
#define CSRT 512
#define CHUNK 338    // ceil(NN/296)
#define EMB_B 50000  // embed blocks (NN*HD/256)
#define PK_B 512     // pack blocks per weight tensor

// ---------------- PTX helpers (all plain-sm_103 legal) -------------------------
__device__ __forceinline__ uint32_t smem_u32(const void* p) {
    uint32_t a;
    asm("{ .reg .u64 t; cvta.to.shared.u64 t, %1; cvt.u32.u64 %0, t; }" : "=r"(a) : "l"(p));
    return a;
}
#define LDSM4(r, a) \
    asm volatile("ldmatrix.sync.aligned.m8n8.x4.shared.b16 {%0,%1,%2,%3}, [%4];" \
        : "=r"((r)[0]), "=r"((r)[1]), "=r"((r)[2]), "=r"((r)[3]) : "r"(a))
#define MMA16816H(d, a, b0, b1) \
    asm volatile("mma.sync.aligned.m16n8k16.row.col.f32.f16.f16.f32 " \
        "{%0,%1,%2,%3}, {%4,%5,%6,%7}, {%8,%9}, {%0,%1,%2,%3};" \
        : "+f"((d)[0]), "+f"((d)[1]), "+f"((d)[2]), "+f"((d)[3]) \
        : "r"((a)[0]), "r"((a)[1]), "r"((a)[2]), "r"((a)[3]), "r"(b0), "r"(b1))
#define CP_ASYNC16(s, g, sz) \
    asm volatile("cp.async.cg.shared.global [%0], [%1], 16, %2;" :: "r"(s), "l"(g), "r"(sz))
#define CP_COMMIT() asm volatile("cp.async.commit_group;")
#define CP_WAIT0()  asm volatile("cp.async.wait_group 0;")
#define CP_WAIT1()  asm volatile("cp.async.wait_group 1;")

// ---------------- device scratch ----------------------------------------------
__device__ __align__(16) float   g_h[NN * HD];               // fp32 h (last layer, pool)
__device__ __align__(16) __half  g_h16[NN * HD];             // fp16 h (gather input)
__device__ __align__(16) __half  g_z16[NN * HD];             // fp16 z (GEMM1 A)
__device__ __align__(16) __half  g_u16[(size_t)NN * HD2];    // fp16 u (GEMM2 A)
__device__ __align__(16) __half  g_B1h[NL * HD2 * HD];       // [l][n=256][k=128] fp16
__device__ __align__(16) __half  g_B2h[NL * HD * HD2];       // [l][n=128][k=256] fp16
__device__ int g_deg[NN], g_rowptr[NN + 1], g_cursor[NN], g_col[NE];
__device__ int g_part[CSRB], g_poff[CSRB];
__device__ volatile int g_bar;                               // reset by k_pool

// ---------------- grid-wide barrier (296 co-resident CTAs, 2/SM) ----------------
__device__ __forceinline__ void gridbar(int phase) {
    __syncthreads();
    if (threadIdx.x == 0) {
        __threadfence();
        atomicAdd((int*)&g_bar, 1);
        while (g_bar < CSRB * phase) { }
        __threadfence();
    }
    __syncthreads();
}

// ---------------- fused CSR build (one launch, 296x512) ------------------------
__global__ void __launch_bounds__(CSRT, 2) k_csr(const int* __restrict__ ei) {
    const int tid = threadIdx.x, bid = blockIdx.x;
    const int gstride = CSRB * CSRT;
    const int gtid = bid * CSRT + tid;
    __shared__ int s[CSRT];

    for (int i = gtid; i < NN; i += gstride) g_deg[i] = 0;
    gridbar(1);
    for (int e = gtid; e < NE; e += gstride) atomicAdd(&g_deg[ei[NE + e]], 1);
    gridbar(2);
    const int start = bid * CHUNK;
    const int end = (start + CHUNK < NN) ? start + CHUNK : NN;
    const int i0 = start + tid;
    int own = (i0 < end) ? g_deg[i0] : 0;
    s[tid] = own;
    __syncthreads();
    for (int off = 1; off < CSRT; off <<= 1) {
        int t = (tid >= off) ? s[tid - off] : 0;
        __syncthreads(); s[tid] += t; __syncthreads();
    }
    const int texcl = s[tid] - own;
    if (tid == CSRT - 1) g_part[bid] = s[tid];
    gridbar(3);
    if (bid == 0 && tid == 0) {
        int r = 0;
        for (int b = 0; b < CSRB; b++) { g_poff[b] = r; r += g_part[b]; }
    }
    gridbar(4);
    if (i0 < end) {
        int run = g_poff[bid] + texcl;
        g_rowptr[i0] = run;
        g_cursor[i0] = run;
    }
    if (gtid == 0) g_rowptr[NN] = NE;
    gridbar(5);
    for (int e = gtid; e < NE; e += gstride) {
        int p = atomicAdd(&g_cursor[ei[NE + e]], 1);
        g_col[p] = ei[e];
    }
}

// ---------------- fused embed + pack W1 + pack W2 --------------------------------
__global__ void k_embed_pack(const float* __restrict__ x, const float* __restrict__ Wemb,
                             const float* __restrict__ bemb,
                             const float* __restrict__ W1, const float* __restrict__ W2) {
    int bid = blockIdx.x;
    int tid = threadIdx.x;
    if (bid < EMB_B) {
        int idx = bid * 256 + tid;
        int n = idx >> 7, c = idx & 127;
        const float* xr = x + n * 9;
        float acc = bemb[c];
#pragma unroll
        for (int k = 0; k < 9; k++) acc = fmaf(xr[k], Wemb[k * HD + c], acc);
        g_h16[idx] = __float2half(acc);
    } else if (bid < EMB_B + PK_B) {
        int idx = (bid - EMB_B) * 256 + tid;        // NL*256*128
        int l = idx / (HD2 * HD), rem = idx % (HD2 * HD);
        int n = rem / HD, k = rem % HD;
        float w = W1[((size_t)l * HD + k) * HD2 + n];
        g_B1h[(size_t)l * HD2 * HD + (size_t)n * HD + k] = __float2half(w);
    } else {
        int idx = (bid - EMB_B - PK_B) * 256 + tid; // NL*128*256
        int l = idx / (HD * HD2), rem = idx % (HD * HD2);
        int n = rem / HD2, k = rem % HD2;
        float w = W2[((size_t)l * HD2 + k) * HD + n];
        g_B2h[(size_t)l * HD * HD2 + (size_t)n * HD2 + k] = __float2half(w);
    }
}

// ---------------- GIN aggregation: fp16 gather, fp32 accumulate (R12 form) ------
__global__ void k_agg(const float* __restrict__ eps, int l) {
    int node = (blockIdx.x * blockDim.x + threadIdx.x) >> 5;
    if (node >= NN) return;
    int lane = threadIdx.x & 31;
    const uint2* h16 = (const uint2*)g_h16;
    float sc = 1.0f + eps[l];
    uint2 sv = h16[(size_t)node * 32 + lane];
    float2 f0 = __half22float2(*(__half2*)&sv.x);
    float2 f1 = __half22float2(*(__half2*)&sv.y);
    float ax = f0.x * sc, ay = f0.y * sc, az = f1.x * sc, aw = f1.y * sc;
    int j = g_rowptr[node], e = g_rowptr[node + 1];
    for (; j + 3 < e; j += 4) {
        uint2 v0 = h16[(size_t)g_col[j]     * 32 + lane];
        uint2 v1 = h16[(size_t)g_col[j + 1] * 32 + lane];
        uint2 v2 = h16[(size_t)g_col[j + 2] * 32 + lane];
        uint2 v3 = h16[(size_t)g_col[j + 3] * 32 + lane];
        float2 f;
        f = __half22float2(*(__half2*)&v0.x); ax += f.x; ay += f.y;
        f = __half22float2(*(__half2*)&v0.y); az += f.x; aw += f.y;
        f = __half22float2(*(__half2*)&v1.x); ax += f.x; ay += f.y;
        f = __half22float2(*(__half2*)&v1.y); az += f.x; aw += f.y;
        f = __half22float2(*(__half2*)&v2.x); ax += f.x; ay += f.y;
        f = __half22float2(*(__half2*)&v2.y); az += f.x; aw += f.y;
        f = __half22float2(*(__half2*)&v3.x); ax += f.x; ay += f.y;
        f = __half22float2(*(__half2*)&v3.y); az += f.x; aw += f.y;
    }
    for (; j < e; j++) {
        uint2 v = h16[(size_t)g_col[j] * 32 + lane];
        float2 f;
        f = __half22float2(*(__half2*)&v.x); ax += f.x; ay += f.y;
        f = __half22float2(*(__half2*)&v.y); az += f.x; aw += f.y;
    }
    __half2 p0 = __floats2half2_rn(ax, ay);
    __half2 p1 = __floats2half2_rn(az, aw);
    uint2 ov = make_uint2(*(uint32_t*)&p0, *(uint32_t*)&p1);
    __stcs((uint2*)(g_z16 + (size_t)node * HD) + lane, ov);
}

// ---------------- HMMA GEMM + BN + ReLU (B fragments via direct LDG) ------------
// MODE 0: u16 = relu(BN(z @ W1)), KDIM=128, NOUT=256
// MODE 1: h16 (+h fp32 if last) = relu(BN(u @ W2)), KDIM=256, NOUT=128
// 128-thread CTAs, 2 per SM (independent barrier domains). 32-row tiles
// (100000/32 = 3125 exact, no bounds checks). Warp wn covers NOUT/4 cols.
// B fragments loaded straight from packed [n][k] gmem per the PTX m16n8k16
// B layout: b0 = halves (k0, k0+1) at n*K + k0, k0 = (lane%4)*2 + ks*16; b1 = +8.
template <int KDIM, int NOUT, int MODE>
__global__ void __launch_bounds__(128, 2)
k_gemm_mma(int l, int last, const float* __restrict__ bb, const float* __restrict__ gm,
           const float* __restrict__ bt, const float* __restrict__ mn,
           const float* __restrict__ vr) {
    constexpr int PC  = KDIM * 2 + 16;   // A row pitch (bytes)
    constexpr int KS  = KDIM / 16;       // k16 steps
    constexpr int NW  = NOUT / 4;        // warp n-width
    constexpr int NT  = NW / 8;          // n8-tiles per warp
    constexpr int RCA = KDIM / 8;        // uint4 per A row
    constexpr int ACH = 32 * PC;         // A buffer bytes (32 rows)
    constexpr int SAC = 2 * ACH;
    constexpr int SCC = SAC + NOUT * 4;

    extern __shared__ char smem[];
    const uint32_t sb = smem_u32(smem);
    const int tid = threadIdx.x, wn = tid >> 5, lane = tid & 31;
    const uint32_t lrow = (lane & 15), lcol = (lane >> 4) * 16;

    const __half* in = (MODE == 0) ? g_z16 : g_u16;
    const __half* __restrict__ Bsrc = (MODE == 0)
        ? (g_B1h + (size_t)l * HD2 * HD)
        : (g_B2h + (size_t)l * HD * HD2);

    // BN constants
    for (int c = tid; c < NOUT; c += 128) {
        float a = gm[c] * rsqrtf(vr[c] + 1e-5f);
        ((float*)(smem + SAC))[c] = a;
        ((float*)(smem + SCC))[c] = fmaf(a, bb[c] - mn[c], bt[c]);
    }

    // B fragments: direct gmem loads (L2-resident weights), tile-invariant
    uint32_t bfr[KS][NT / 2][4];
    {
        const int kq = (lane & 3) * 2, nq = lane >> 2;
#pragma unroll
        for (int ks = 0; ks < KS; ks++)
#pragma unroll
            for (int np = 0; np < NT / 2; np++) {
                int nb = wn * NW + np * 16;
                const __half* p0 = Bsrc + (size_t)(nb + nq) * KDIM + ks * 16 + kq;
                const __half* p1 = p0 + (size_t)8 * KDIM;
                bfr[ks][np][0] = *(const uint32_t*)p0;
                bfr[ks][np][2] = *(const uint32_t*)(p0 + 8);
                bfr[ks][np][1] = *(const uint32_t*)p1;
                bfr[ks][np][3] = *(const uint32_t*)(p1 + 8);
            }
    }
    __syncthreads();

    const float* Ac = (const float*)(smem + SAC);
    const float* Cc = (const float*)(smem + SCC);
    const int tiles = NN / 32;                    // 3125, exact
    const int myTiles = (tiles > (int)blockIdx.x)
                        ? (tiles - blockIdx.x + gridDim.x - 1) / gridDim.x : 0;

    auto issueA = [&](int t, int buf) {
        int row0 = (blockIdx.x + t * gridDim.x) * 32;
        for (int c = tid; c < 32 * RCA; c += 128) {
            int r = c / RCA, q = c % RCA;
            const void* g = in + (size_t)(row0 + r) * KDIM + q * 8;
            CP_ASYNC16(sb + buf * ACH + r * PC + q * 16, g, 16);
        }
        CP_COMMIT();
    };

    if (myTiles > 0) issueA(0, 0);

    for (int t = 0; t < myTiles; t++) {
        const int buf = t & 1;
        const int row0 = (blockIdx.x + t * gridDim.x) * 32;
        __syncthreads();
        if (t + 1 < myTiles) { issueA(t + 1, (t + 1) & 1); CP_WAIT1(); }
        else                 { CP_WAIT0(); }
        __syncthreads();

        float acc[2][NT][4];
#pragma unroll
        for (int i = 0; i < 2; i++)
#pragma unroll
            for (int j = 0; j < NT; j++)
#pragma unroll
                for (int q = 0; q < 4; q++) acc[i][j][q] = 0.f;

#pragma unroll
        for (int ks = 0; ks < KS; ks++) {
            uint32_t ah[2][4];
#pragma unroll
            for (int i = 0; i < 2; i++)
                LDSM4(ah[i], sb + buf * ACH + (i * 16 + lrow) * PC + ks * 32 + lcol);
#pragma unroll
            for (int np = 0; np < NT / 2; np++)
#pragma unroll
                for (int i = 0; i < 2; i++) {
                    MMA16816H(acc[i][2 * np],     ah[i], bfr[ks][np][0], bfr[ks][np][2]);
                    MMA16816H(acc[i][2 * np + 1], ah[i], bfr[ks][np][1], bfr[ks][np][3]);
                }
        }

        // epilogue: BN + ReLU (rows always in range: 3125*32 = NN exactly)
#pragma unroll
        for (int i = 0; i < 2; i++) {
#pragma unroll
            for (int j = 0; j < NT; j++) {
                int r0 = row0 + i * 16 + (lane >> 2);
                int r1 = r0 + 8;
                int c = wn * NW + j * 8 + (lane & 3) * 2;
                float a0 = Ac[c], a1 = Ac[c + 1], c0 = Cc[c], c1 = Cc[c + 1];
                float y00 = fmaxf(fmaf(acc[i][j][0], a0, c0), 0.f);
                float y01 = fmaxf(fmaf(acc[i][j][1], a1, c1), 0.f);
                float y10 = fmaxf(fmaf(acc[i][j][2], a0, c0), 0.f);
                float y11 = fmaxf(fmaf(acc[i][j][3], a1, c1), 0.f);
                if (MODE == 0) {
                    __half2 p0 = __floats2half2_rn(y00, y01);
                    __half2 p1 = __floats2half2_rn(y10, y11);
                    __stcs((uint32_t*)(g_u16 + (size_t)r0 * HD2 + c), *(uint32_t*)&p0);
                    __stcs((uint32_t*)(g_u16 + (size_t)r1 * HD2 + c), *(uint32_t*)&p1);
                } else {
                    __half2 p0 = __floats2half2_rn(y00, y01);
                    __half2 p1 = __floats2half2_rn(y10, y11);
                    *(uint32_t*)(g_h16 + (size_t)r0 * HD + c) = *(uint32_t*)&p0;
                    *(uint32_t*)(g_h16 + (size_t)r1 * HD + c) = *(uint32_t*)&p1;
                    if (last) {
                        *(float2*)(g_h + (size_t)r0 * HD + c) = make_float2(y00, y01);
                        *(float2*)(g_h + (size_t)r1 * HD + c) = make_float2(y10, y11);
                    }
                }
            }
        }
    }
}

// ---------------- global mean pool (+ barrier reset for next replay) ----------
__global__ void k_pool(const int* __restrict__ batch, float* __restrict__ out) {
    if (blockIdx.x == 0 && threadIdx.x == 0) g_bar = 0;
    int g = blockIdx.x, c = threadIdx.x;
    int lo = 0, hi = NN;
    while (lo < hi) { int mid = (lo + hi) >> 1; if (batch[mid] < g) lo = mid + 1; else hi = mid; }
    int start = lo;
    lo = start; hi = NN;
    while (lo < hi) { int mid = (lo + hi) >> 1; if (batch[mid] < g + 1) lo = mid + 1; else hi = mid; }
    int end = lo;
    float acc = 0.f;
    int n = start;
    for (; n + 3 < end; n += 4) {
        acc += g_h[(n + 0) * HD + c];
        acc += g_h[(n + 1) * HD + c];
        acc += g_h[(n + 2) * HD + c];
        acc += g_h[(n + 3) * HD + c];
    }
    for (; n < end; n++) acc += g_h[n * HD + c];
    float cnt = (float)(end - start);
    out[g * HD + c] = acc / fmaxf(cnt, 1.f);
}

// ---------------- launch --------------------------------------------------------
extern "C" void kernel_launch(void* const* d_in, const int* in_sizes, int n_in,
                              void* d_out, int out_size) {
    const float* x    = (const float*)d_in[0];
    const int*   ei   = (const int*)d_in[1];
    const int*   bat  = (const int*)d_in[2];
    const float* Wemb = (const float*)d_in[3];
    const float* bemb = (const float*)d_in[4];
    const float* eps  = (const float*)d_in[5];
    const float* W1   = (const float*)d_in[6];
    const float* b1   = (const float*)d_in[7];
    const float* g1   = (const float*)d_in[8];
    const float* be1  = (const float*)d_in[9];
    const float* m1   = (const float*)d_in[10];
    const float* v1   = (const float*)d_in[11];
    const float* W2   = (const float*)d_in[12];
    const float* b2   = (const float*)d_in[13];
    const float* g2   = (const float*)d_in[14];
    const float* be2  = (const float*)d_in[15];
    const float* m2   = (const float*)d_in[16];
    const float* v2   = (const float*)d_in[17];
    float* out = (float*)d_out;

    // smem: MODE0 = 2*32*272 + 2048 = 19456 B; MODE1 = 2*32*528 + 1024 = 34816 B
    const int sm0 = 19456, sm1 = 34816;

    // order: embed+packs(1), csr(2), agg(3), gemm1(4) -> ncu (launch #4) profiles gemm1
    k_embed_pack<<<EMB_B + 2 * PK_B, 256>>>(x, Wemb, bemb, W1, W2);  // 1
    k_csr<<<CSRB, CSRT>>>(ei);                                       // 2

    for (int l = 0; l < NL; l++) {
        k_agg<<<(NN + 7) / 8, 256>>>(eps, l);                        // 3 (l=0)
        k_gemm_mma<128, 256, 0><<<296, 128, sm0>>>(l, 0, b1 + l * HD2, g1 + l * HD2,
                                                   be1 + l * HD2, m1 + l * HD2, v1 + l * HD2);
        k_gemm_mma<256, 128, 1><<<296, 128, sm1>>>(l, (l == NL - 1) ? 1 : 0,
                                                   b2 + l * HD, g2 + l * HD,
                                                   be2 + l * HD, m2 + l * HD, v2 + l * HD);
    }

    k_pool<<<NG, 128>>>(bat, out);
}

// round 17
// speedup vs baseline: 2.3680x; 1.0027x over previous
#include <cuda_runtime.h>
#include <cuda_fp16.h>
#include <cstdint>

#define NN 100000
#define NE 3200000
#define HD 128
#define HD2 256
#define NL 4
#define NG 512
#define CSRB 296
#define CSRT 512
#define CHUNK 338    // ceil(NN/296)
#define EMB_B 50000  // embed blocks (NN*HD/256)
#define PK_B 512     // pack blocks per weight tensor

// ---------------- PTX helpers (all plain-sm_103 legal) -------------------------
__device__ __forceinline__ uint32_t smem_u32(const void* p) {
    uint32_t a;
    asm("{ .reg .u64 t; cvta.to.shared.u64 t, %1; cvt.u32.u64 %0, t; }" : "=r"(a) : "l"(p));
    return a;
}
#define LDSM4(r, a) \
    asm volatile("ldmatrix.sync.aligned.m8n8.x4.shared.b16 {%0,%1,%2,%3}, [%4];" \
        : "=r"((r)[0]), "=r"((r)[1]), "=r"((r)[2]), "=r"((r)[3]) : "r"(a))
#define MMA16816H(d, a, b0, b1) \
    asm volatile("mma.sync.aligned.m16n8k16.row.col.f32.f16.f16.f32 " \
        "{%0,%1,%2,%3}, {%4,%5,%6,%7}, {%8,%9}, {%0,%1,%2,%3};" \
        : "+f"((d)[0]), "+f"((d)[1]), "+f"((d)[2]), "+f"((d)[3]) \
        : "r"((a)[0]), "r"((a)[1]), "r"((a)[2]), "r"((a)[3]), "r"(b0), "r"(b1))
#define CP_ASYNC16(s, g, sz) \
    asm volatile("cp.async.cg.shared.global [%0], [%1], 16, %2;" :: "r"(s), "l"(g), "r"(sz))
#define CP_COMMIT() asm volatile("cp.async.commit_group;")
#define CP_WAIT0()  asm volatile("cp.async.wait_group 0;")
#define CP_WAIT1()  asm volatile("cp.async.wait_group 1;")

// ---------------- device scratch ----------------------------------------------
__device__ __align__(16) float   g_h[NN * HD];               // fp32 h (last layer, pool)
__device__ __align__(16) __half  g_h16[NN * HD];             // fp16 h (gather input)
__device__ __align__(16) __half  g_z16[NN * HD];             // fp16 z (GEMM1 A)
__device__ __align__(16) __half  g_u16[(size_t)NN * HD2];    // fp16 u (GEMM2 A)
__device__ __align__(16) __half  g_B1h[NL * HD2 * HD];       // [l][n=256][k=128] fp16
__device__ __align__(16) __half  g_B2h[NL * HD * HD2];       // [l][n=128][k=256] fp16
__device__ int g_deg[NN], g_rowptr[NN + 1], g_cursor[NN], g_col[NE];
__device__ int g_part[CSRB], g_poff[CSRB];
__device__ volatile int g_bar;                               // reset by k_pool

// ---------------- grid-wide barrier (296 co-resident CTAs, 2/SM) ----------------
__device__ __forceinline__ void gridbar(int phase) {
    __syncthreads();
    if (threadIdx.x == 0) {
        __threadfence();
        atomicAdd((int*)&g_bar, 1);
        while (g_bar < CSRB * phase) { }
        __threadfence();
    }
    __syncthreads();
}

// ---------------- fused CSR build (one launch, 296x512) ------------------------
__global__ void __launch_bounds__(CSRT, 2) k_csr(const int* __restrict__ ei) {
    const int tid = threadIdx.x, bid = blockIdx.x;
    const int gstride = CSRB * CSRT;
    const int gtid = bid * CSRT + tid;
    __shared__ int s[CSRT];

    for (int i = gtid; i < NN; i += gstride) g_deg[i] = 0;
    gridbar(1);
    for (int e = gtid; e < NE; e += gstride) atomicAdd(&g_deg[ei[NE + e]], 1);
    gridbar(2);
    const int start = bid * CHUNK;
    const int end = (start + CHUNK < NN) ? start + CHUNK : NN;
    const int i0 = start + tid;
    int own = (i0 < end) ? g_deg[i0] : 0;
    s[tid] = own;
    __syncthreads();
    for (int off = 1; off < CSRT; off <<= 1) {
        int t = (tid >= off) ? s[tid - off] : 0;
        __syncthreads(); s[tid] += t; __syncthreads();
    }
    const int texcl = s[tid] - own;
    if (tid == CSRT - 1) g_part[bid] = s[tid];
    gridbar(3);
    if (bid == 0 && tid == 0) {
        int r = 0;
        for (int b = 0; b < CSRB; b++) { g_poff[b] = r; r += g_part[b]; }
    }
    gridbar(4);
    if (i0 < end) {
        int run = g_poff[bid] + texcl;
        g_rowptr[i0] = run;
        g_cursor[i0] = run;
    }
    if (gtid == 0) g_rowptr[NN] = NE;
    gridbar(5);
    for (int e = gtid; e < NE; e += gstride) {
        int p = atomicAdd(&g_cursor[ei[NE + e]], 1);
        g_col[p] = ei[e];
    }
}

// ---------------- fused embed + pack W1 + pack W2 --------------------------------
__global__ void k_embed_pack(const float* __restrict__ x, const float* __restrict__ Wemb,
                             const float* __restrict__ bemb,
                             const float* __restrict__ W1, const float* __restrict__ W2) {
    int bid = blockIdx.x;
    int tid = threadIdx.x;
    if (bid < EMB_B) {
        int idx = bid * 256 + tid;
        int n = idx >> 7, c = idx & 127;
        const float* xr = x + n * 9;
        float acc = bemb[c];
#pragma unroll
        for (int k = 0; k < 9; k++) acc = fmaf(xr[k], Wemb[k * HD + c], acc);
        g_h16[idx] = __float2half(acc);
    } else if (bid < EMB_B + PK_B) {
        int idx = (bid - EMB_B) * 256 + tid;        // NL*256*128
        int l = idx / (HD2 * HD), rem = idx % (HD2 * HD);
        int n = rem / HD, k = rem % HD;
        float w = W1[((size_t)l * HD + k) * HD2 + n];
        g_B1h[(size_t)l * HD2 * HD + (size_t)n * HD + k] = __float2half(w);
    } else {
        int idx = (bid - EMB_B - PK_B) * 256 + tid; // NL*128*256
        int l = idx / (HD * HD2), rem = idx % (HD * HD2);
        int n = rem / HD2, k = rem % HD2;
        float w = W2[((size_t)l * HD2 + k) * HD + n];
        g_B2h[(size_t)l * HD * HD2 + (size_t)n * HD2 + k] = __float2half(w);
    }
}

// ---------------- GIN aggregation: fp16 gather, fp32 accumulate -----------------
__global__ void k_agg(const float* __restrict__ eps, int l) {
    int node = (blockIdx.x * blockDim.x + threadIdx.x) >> 5;
    if (node >= NN) return;
    int lane = threadIdx.x & 31;
    const uint2* h16 = (const uint2*)g_h16;
    float sc = 1.0f + eps[l];
    uint2 sv = h16[(size_t)node * 32 + lane];
    float2 f0 = __half22float2(*(__half2*)&sv.x);
    float2 f1 = __half22float2(*(__half2*)&sv.y);
    float ax = f0.x * sc, ay = f0.y * sc, az = f1.x * sc, aw = f1.y * sc;
    int j = g_rowptr[node], e = g_rowptr[node + 1];
    for (; j + 3 < e; j += 4) {
        uint2 v0 = h16[(size_t)g_col[j]     * 32 + lane];
        uint2 v1 = h16[(size_t)g_col[j + 1] * 32 + lane];
        uint2 v2 = h16[(size_t)g_col[j + 2] * 32 + lane];
        uint2 v3 = h16[(size_t)g_col[j + 3] * 32 + lane];
        float2 f;
        f = __half22float2(*(__half2*)&v0.x); ax += f.x; ay += f.y;
        f = __half22float2(*(__half2*)&v0.y); az += f.x; aw += f.y;
        f = __half22float2(*(__half2*)&v1.x); ax += f.x; ay += f.y;
        f = __half22float2(*(__half2*)&v1.y); az += f.x; aw += f.y;
        f = __half22float2(*(__half2*)&v2.x); ax += f.x; ay += f.y;
        f = __half22float2(*(__half2*)&v2.y); az += f.x; aw += f.y;
        f = __half22float2(*(__half2*)&v3.x); ax += f.x; ay += f.y;
        f = __half22float2(*(__half2*)&v3.y); az += f.x; aw += f.y;
    }
    for (; j < e; j++) {
        uint2 v = h16[(size_t)g_col[j] * 32 + lane];
        float2 f;
        f = __half22float2(*(__half2*)&v.x); ax += f.x; ay += f.y;
        f = __half22float2(*(__half2*)&v.y); az += f.x; aw += f.y;
    }
    __half2 p0 = __floats2half2_rn(ax, ay);
    __half2 p1 = __floats2half2_rn(az, aw);
    uint2 ov = make_uint2(*(uint32_t*)&p0, *(uint32_t*)&p1);
    // default store: keep z16 L2-resident for gemm1 (NOT __stcs)
    ((uint2*)(g_z16 + (size_t)node * HD))[lane] = ov;
}

// ---------------- HMMA GEMM + BN + ReLU (B fragments via direct LDG) ------------
// MODE 0: u16 = relu(BN(z @ W1)), KDIM=128, NOUT=256
// MODE 1: h16 (+h fp32 if last) = relu(BN(u @ W2)), KDIM=256, NOUT=128
// 128-thread CTAs, 2 per SM. 32-row tiles (3125 exact). Triple-buffered A,
// ONE __syncthreads per tile: wait(<=1) -> sync -> issue t+2 -> compute t.
template <int KDIM, int NOUT, int MODE>
__global__ void __launch_bounds__(128, 2)
k_gemm_mma(int l, int last, const float* __restrict__ bb, const float* __restrict__ gm,
           const float* __restrict__ bt, const float* __restrict__ mn,
           const float* __restrict__ vr) {
    constexpr int PC  = KDIM * 2 + 16;   // A row pitch (bytes)
    constexpr int KS  = KDIM / 16;       // k16 steps
    constexpr int NW  = NOUT / 4;        // warp n-width
    constexpr int NT  = NW / 8;          // n8-tiles per warp
    constexpr int RCA = KDIM / 8;        // uint4 per A row
    constexpr int ACH = 32 * PC;         // A buffer bytes (32 rows)
    constexpr int SAC = 3 * ACH;
    constexpr int SCC = SAC + NOUT * 4;

    extern __shared__ char smem[];
    const uint32_t sb = smem_u32(smem);
    const int tid = threadIdx.x, wn = tid >> 5, lane = tid & 31;
    const uint32_t lrow = (lane & 15), lcol = (lane >> 4) * 16;

    const __half* in = (MODE == 0) ? g_z16 : g_u16;
    const __half* __restrict__ Bsrc = (MODE == 0)
        ? (g_B1h + (size_t)l * HD2 * HD)
        : (g_B2h + (size_t)l * HD * HD2);

    // BN constants
    for (int c = tid; c < NOUT; c += 128) {
        float a = gm[c] * rsqrtf(vr[c] + 1e-5f);
        ((float*)(smem + SAC))[c] = a;
        ((float*)(smem + SCC))[c] = fmaf(a, bb[c] - mn[c], bt[c]);
    }

    // B fragments: direct gmem loads (L2-resident weights), tile-invariant
    uint32_t bfr[KS][NT / 2][4];
    {
        const int kq = (lane & 3) * 2, nq = lane >> 2;
#pragma unroll
        for (int ks = 0; ks < KS; ks++)
#pragma unroll
            for (int np = 0; np < NT / 2; np++) {
                int nb = wn * NW + np * 16;
                const __half* p0 = Bsrc + (size_t)(nb + nq) * KDIM + ks * 16 + kq;
                const __half* p1 = p0 + (size_t)8 * KDIM;
                bfr[ks][np][0] = *(const uint32_t*)p0;
                bfr[ks][np][2] = *(const uint32_t*)(p0 + 8);
                bfr[ks][np][1] = *(const uint32_t*)p1;
                bfr[ks][np][3] = *(const uint32_t*)(p1 + 8);
            }
    }
    __syncthreads();

    const float* Ac = (const float*)(smem + SAC);
    const float* Cc = (const float*)(smem + SCC);
    const int tiles = NN / 32;                    // 3125, exact
    const int myTiles = (tiles > (int)blockIdx.x)
                        ? (tiles - blockIdx.x + gridDim.x - 1) / gridDim.x : 0;

    auto issueA = [&](int t, int buf) {
        int row0 = (blockIdx.x + t * gridDim.x) * 32;
        for (int c = tid; c < 32 * RCA; c += 128) {
            int r = c / RCA, q = c % RCA;
            const void* g = in + (size_t)(row0 + r) * KDIM + q * 8;
            CP_ASYNC16(sb + buf * ACH + r * PC + q * 16, g, 16);
        }
        CP_COMMIT();
    };

    if (myTiles > 0) issueA(0, 0);
    if (myTiles > 1) issueA(1, 1);

    for (int t = 0; t < myTiles; t++) {
        const int buf = t % 3;
        const int row0 = (blockIdx.x + t * gridDim.x) * 32;
        if (t + 1 < myTiles) CP_WAIT1(); else CP_WAIT0();   // A(t) landed
        __syncthreads();                                     // all warps past t-1
        if (t + 2 < myTiles) issueA(t + 2, (t + 2) % 3);     // buf free since t-1

        float acc[2][NT][4];
#pragma unroll
        for (int i = 0; i < 2; i++)
#pragma unroll
            for (int j = 0; j < NT; j++)
#pragma unroll
                for (int q = 0; q < 4; q++) acc[i][j][q] = 0.f;

#pragma unroll
        for (int ks = 0; ks < KS; ks++) {
            uint32_t ah[2][4];
#pragma unroll
            for (int i = 0; i < 2; i++)
                LDSM4(ah[i], sb + buf * ACH + (i * 16 + lrow) * PC + ks * 32 + lcol);
#pragma unroll
            for (int np = 0; np < NT / 2; np++)
#pragma unroll
                for (int i = 0; i < 2; i++) {
                    MMA16816H(acc[i][2 * np],     ah[i], bfr[ks][np][0], bfr[ks][np][2]);
                    MMA16816H(acc[i][2 * np + 1], ah[i], bfr[ks][np][1], bfr[ks][np][3]);
                }
        }

        // epilogue: BN + ReLU (rows always in range: 3125*32 = NN exactly)
#pragma unroll
        for (int i = 0; i < 2; i++) {
#pragma unroll
            for (int j = 0; j < NT; j++) {
                int r0 = row0 + i * 16 + (lane >> 2);
                int r1 = r0 + 8;
                int c = wn * NW + j * 8 + (lane & 3) * 2;
                float a0 = Ac[c], a1 = Ac[c + 1], c0 = Cc[c], c1 = Cc[c + 1];
                float y00 = fmaxf(fmaf(acc[i][j][0], a0, c0), 0.f);
                float y01 = fmaxf(fmaf(acc[i][j][1], a1, c1), 0.f);
                float y10 = fmaxf(fmaf(acc[i][j][2], a0, c0), 0.f);
                float y11 = fmaxf(fmaf(acc[i][j][3], a1, c1), 0.f);
                __half2 p0 = __floats2half2_rn(y00, y01);
                __half2 p1 = __floats2half2_rn(y10, y11);
                if (MODE == 0) {
                    // default stores: keep u16 L2-resident for gemm2 (NOT __stcs)
                    *(uint32_t*)(g_u16 + (size_t)r0 * HD2 + c) = *(uint32_t*)&p0;
                    *(uint32_t*)(g_u16 + (size_t)r1 * HD2 + c) = *(uint32_t*)&p1;
                } else {
                    *(uint32_t*)(g_h16 + (size_t)r0 * HD + c) = *(uint32_t*)&p0;
                    *(uint32_t*)(g_h16 + (size_t)r1 * HD + c) = *(uint32_t*)&p1;
                    if (last) {
                        *(float2*)(g_h + (size_t)r0 * HD + c) = make_float2(y00, y01);
                        *(float2*)(g_h + (size_t)r1 * HD + c) = make_float2(y10, y11);
                    }
                }
            }
        }
    }
}

// ---------------- global mean pool (+ barrier reset for next replay) ----------
__global__ void k_pool(const int* __restrict__ batch, float* __restrict__ out) {
    if (blockIdx.x == 0 && threadIdx.x == 0) g_bar = 0;
    int g = blockIdx.x, c = threadIdx.x;
    int lo = 0, hi = NN;
    while (lo < hi) { int mid = (lo + hi) >> 1; if (batch[mid] < g) lo = mid + 1; else hi = mid; }
    int start = lo;
    lo = start; hi = NN;
    while (lo < hi) { int mid = (lo + hi) >> 1; if (batch[mid] < g + 1) lo = mid + 1; else hi = mid; }
    int end = lo;
    float acc = 0.f;
    int n = start;
    for (; n + 3 < end; n += 4) {
        acc += g_h[(n + 0) * HD + c];
        acc += g_h[(n + 1) * HD + c];
        acc += g_h[(n + 2) * HD + c];
        acc += g_h[(n + 3) * HD + c];
    }
    for (; n < end; n++) acc += g_h[n * HD + c];
    float cnt = (float)(end - start);
    out[g * HD + c] = acc / fmaxf(cnt, 1.f);
}

// ---------------- launch --------------------------------------------------------
extern "C" void kernel_launch(void* const* d_in, const int* in_sizes, int n_in,
                              void* d_out, int out_size) {
    const float* x    = (const float*)d_in[0];
    const int*   ei   = (const int*)d_in[1];
    const int*   bat  = (const int*)d_in[2];
    const float* Wemb = (const float*)d_in[3];
    const float* bemb = (const float*)d_in[4];
    const float* eps  = (const float*)d_in[5];
    const float* W1   = (const float*)d_in[6];
    const float* b1   = (const float*)d_in[7];
    const float* g1   = (const float*)d_in[8];
    const float* be1  = (const float*)d_in[9];
    const float* m1   = (const float*)d_in[10];
    const float* v1   = (const float*)d_in[11];
    const float* W2   = (const float*)d_in[12];
    const float* b2   = (const float*)d_in[13];
    const float* g2   = (const float*)d_in[14];
    const float* be2  = (const float*)d_in[15];
    const float* m2   = (const float*)d_in[16];
    const float* v2   = (const float*)d_in[17];
    float* out = (float*)d_out;

    // smem: MODE0 = 3*32*272 + 2048 = 28160 B; MODE1 = 3*32*528 + 1024 = 51712 B
    // MODE1 > 48KB default -> MUST opt in (missing this broke R16's launch)
    const int sm0 = 28160, sm1 = 51712;
    cudaFuncSetAttribute(k_gemm_mma<128, 256, 0>, cudaFuncAttributeMaxDynamicSharedMemorySize, sm0);
    cudaFuncSetAttribute(k_gemm_mma<256, 128, 1>, cudaFuncAttributeMaxDynamicSharedMemorySize, sm1);

    // order: embed+packs(1), csr(2), agg(3), gemm1(4) -> ncu (launch #4) profiles gemm1
    k_embed_pack<<<EMB_B + 2 * PK_B, 256>>>(x, Wemb, bemb, W1, W2);  // 1
    k_csr<<<CSRB, CSRT>>>(ei);                                       // 2

    for (int l = 0; l < NL; l++) {
        k_agg<<<(NN + 7) / 8, 256>>>(eps, l);                        // 3 (l=0)
        k_gemm_mma<128, 256, 0><<<296, 128, sm0>>>(l, 0, b1 + l * HD2, g1 + l * HD2,
                                                   be1 + l * HD2, m1 + l * HD2, v1 + l * HD2);
        k_gemm_mma<256, 128, 1><<<296, 128, sm1>>>(l, (l == NL - 1) ? 1 : 0,
                                                   b2 + l * HD, g2 + l * HD,
                                                   be2 + l * HD, m2 + l * HD, v2 + l * HD);
    }

    k_pool<<<NG, 128>>>(bat, out);
}